// round 2
// baseline (speedup 1.0000x reference)
#include <cuda_runtime.h>
#include <cstdint>
#include <cstddef>

#define C 128
#define CC (C * C)
#define NU 100000
#define NI 200000
#define NEDGE 1500000

// ---------------------------------------------------------------------------
// Scratch (device globals; no runtime allocation allowed)
// ---------------------------------------------------------------------------
__device__ __align__(256) float g_xu[2][(size_t)NU * C];
__device__ __align__(256) float g_xi[2][(size_t)NI * C];
__device__ __align__(256) float g_msg_u[(size_t)NU * C];
__device__ __align__(256) float g_msg_i[(size_t)NI * C];
__device__ __align__(256) int   g_cnt_u[NU];
__device__ __align__(256) int   g_cnt_i[NI];
__device__ __align__(256) float g_inv_u[NU];
__device__ __align__(256) float g_inv_i[NI];

// ---------------------------------------------------------------------------
// f32x2 helpers (Blackwell packed fp32: 2x FFMA throughput vs 3-reg FFMA)
// ---------------------------------------------------------------------------
__device__ __forceinline__ unsigned long long pack2(float x, float y) {
    unsigned long long r;
    asm("mov.b64 %0, {%1, %2};" : "=l"(r) : "f"(x), "f"(y));
    return r;
}
__device__ __forceinline__ void unpack2(unsigned long long v, float& x, float& y) {
    asm("mov.b64 {%0, %1}, %2;" : "=f"(x), "=f"(y) : "l"(v));
}
__device__ __forceinline__ void ffma2(unsigned long long& d, unsigned long long a,
                                      unsigned long long b) {
    asm("fma.rn.f32x2 %0, %1, %2, %0;" : "+l"(d) : "l"(a), "l"(b));
}
__device__ __forceinline__ float f4get(float4 v, int i) {
    return i == 0 ? v.x : (i == 1 ? v.y : (i == 2 ? v.z : v.w));
}
// vector reduction (no return value) — cheaper than atomicAdd round-trip,
// and independent of header-level float4 atomicAdd support.
__device__ __forceinline__ void redg_add_v4(float* addr, float4 v) {
    asm volatile("red.global.add.v4.f32 [%0], {%1, %2, %3, %4};"
                 :: "l"(addr), "f"(v.x), "f"(v.y), "f"(v.z), "f"(v.w)
                 : "memory");
}

// Shared-memory strides (pad 132 floats: 16B-aligned rows, reduced conflicts)
#define SROW 132
#define UPD_SMEM_FLOATS (256 * SROW + 128 * SROW)
#define TE_SMEM_FLOATS  (128 * SROW * 2 + 128 + 64)

// One 128-wide K phase: acc[8][4] += In[node][k] * Wt[k][chan]
// sW: rows [0,128) stride SROW (Wt[k][c]); sIn: [128][SROW] node-major.
__device__ __forceinline__ void mac_phase(const float* sW, const float* sIn,
                                          int ng8, int c0,
                                          unsigned long long acc[8][4]) {
#pragma unroll 1
    for (int kc = 0; kc < 128; kc += 4) {
        float4 a4[8];
#pragma unroll
        for (int r = 0; r < 8; ++r)
            a4[r] = *(const float4*)(sIn + (ng8 + r) * SROW + kc);
#pragma unroll
        for (int kk = 0; kk < 4; ++kk) {
            const float* wr = sW + (kc + kk) * SROW + c0;
            ulonglong2 w01 = *(const ulonglong2*)(wr);
            ulonglong2 w23 = *(const ulonglong2*)(wr + 4);
#pragma unroll
            for (int r = 0; r < 8; ++r) {
                float av = f4get(a4[r], kk);
                unsigned long long a2 = pack2(av, av);
                ffma2(acc[r][0], a2, w01.x);
                ffma2(acc[r][1], a2, w01.y);
                ffma2(acc[r][2], a2, w23.x);
                ffma2(acc[r][3], a2, w23.y);
            }
        }
    }
}

// ---------------------------------------------------------------------------
// Small utility kernels
// ---------------------------------------------------------------------------
__global__ void zero_kernel(float4* __restrict__ p, int n4) {
    int stride = gridDim.x * blockDim.x;
    for (int i = blockIdx.x * blockDim.x + threadIdx.x; i < n4; i += stride)
        p[i] = make_float4(0.f, 0.f, 0.f, 0.f);
}

__global__ void count_kernel(const int* __restrict__ dst, int* __restrict__ cnt, int nE) {
    int stride = gridDim.x * blockDim.x;
    for (int i = blockIdx.x * blockDim.x + threadIdx.x; i < nE; i += stride)
        atomicAdd(cnt + __ldg(dst + i), 1);
}

__global__ void inv_kernel(const int* __restrict__ cnt, float* __restrict__ inv, int n) {
    int i = blockIdx.x * blockDim.x + threadIdx.x;
    if (i < n) inv[i] = 1.0f / (float)max(cnt[i], 1);
}

// warp-per-edge gather + vector reduction scatter-add
__global__ void scatter_kernel(const float* __restrict__ x, const int* __restrict__ src,
                               const int* __restrict__ dst, float* __restrict__ msg,
                               int nE) {
    int lane = threadIdx.x & 31;
    int w = (blockIdx.x * blockDim.x + threadIdx.x) >> 5;
    int nW = (gridDim.x * blockDim.x) >> 5;
    for (int e = w; e < nE; e += nW) {
        int s = __ldg(src + e);
        int d = __ldg(dst + e);
        float4 v = __ldg((const float4*)(x + (size_t)s * C) + lane);
        redg_add_v4(msg + (size_t)d * C + lane * 4, v);
    }
}

// ---------------------------------------------------------------------------
// Temporal encoder: out = x + PE(rel_time) @ W^T + b
// ---------------------------------------------------------------------------
__global__ __launch_bounds__(256, 1)
void temporal_kernel(const float* __restrict__ x, const int* __restrict__ seed_time,
                     const int* __restrict__ node_time, const int* __restrict__ batch,
                     const float* __restrict__ W, const float* __restrict__ bias,
                     float* __restrict__ out, int n_nodes) {
    extern __shared__ float smem[];
    float* sW   = smem;                    // [128][SROW]
    float* sPE  = smem + 128 * SROW;       // [128][SROW]
    float* sRel = sPE + 128 * SROW;        // [128]
    float* sDiv = sRel + 128;              // [64]

    int tid = threadIdx.x;
    int cg = tid & 15, ng = tid >> 4;
    int c0 = cg * 8, ng8 = ng * 8;

    // Wt[k][c] = W[c][k]
    for (int i = tid; i < CC; i += 256) {
        int c = i >> 7, k = i & 127;
        sW[k * SROW + c] = W[i];
    }
    if (tid < 64)
        sDiv[tid] = exp2f(-(float)tid * 0.20762050593046015f);  // 10000^(-j/64)

    unsigned long long bias2[4];
#pragma unroll
    for (int p = 0; p < 4; ++p)
        bias2[p] = pack2(__ldg(bias + c0 + 2 * p), __ldg(bias + c0 + 2 * p + 1));
    __syncthreads();

    int ntiles = (n_nodes + 127) >> 7;
    for (int t = blockIdx.x; t < ntiles; t += gridDim.x) {
        int t0 = t << 7;
        int valid = min(128, n_nodes - t0);
        __syncthreads();  // protect sPE/sRel reuse across tiles

        if (tid < 128) {
            float r = 0.f;
            int n = t0 + tid;
            if (tid < valid) {
                int st = __ldg(seed_time + __ldg(batch + n));
                r = (float)(st - __ldg(node_time + n)) * (1.0f / 86400.0f);
            }
            sRel[tid] = r;
        }
        __syncthreads();

        for (int i = tid; i < 128 * 64; i += 256) {
            int n = i >> 6, j = i & 63;
            float ang = sRel[n] * sDiv[j];
            // explicit range reduction so fast-math sin/cos stays accurate
            float kq = rintf(ang * 0.15915494309189535f);
            ang = fmaf(kq, -6.283185307179586f, ang);
            float sv, cv;
            sincosf(ang, &sv, &cv);
            sPE[n * SROW + 2 * j]     = sv;
            sPE[n * SROW + 2 * j + 1] = cv;
        }
        __syncthreads();

        unsigned long long acc[8][4];
#pragma unroll
        for (int r = 0; r < 8; ++r)
#pragma unroll
            for (int p = 0; p < 4; ++p) acc[r][p] = bias2[p];

        mac_phase(sW, sPE, ng8, c0, acc);

#pragma unroll
        for (int r = 0; r < 8; ++r) {
            int n = ng8 + r;
            if (n < valid) {
                float v[8];
#pragma unroll
                for (int p = 0; p < 4; ++p) unpack2(acc[r][p], v[2 * p], v[2 * p + 1]);
                const float* px = x + (size_t)(t0 + n) * C + c0;
                float4 x0 = __ldg((const float4*)px);
                float4 x1 = __ldg((const float4*)px + 1);
                float* po = out + (size_t)(t0 + n) * C + c0;
                *(float4*)po = make_float4(v[0] + x0.x, v[1] + x0.y, v[2] + x0.z, v[3] + x0.w);
                *(float4*)(po + 4) = make_float4(v[4] + x1.x, v[5] + x1.y, v[6] + x1.z, v[7] + x1.w);
            }
        }
    }
}

// ---------------------------------------------------------------------------
// Layer update: out = relu(LN(msg*inv @ Wl^T + bias + x @ Wr^T))
// ---------------------------------------------------------------------------
__global__ __launch_bounds__(256, 1)
void update_kernel(const float* __restrict__ msg, const float* __restrict__ inv,
                   const float* __restrict__ xin,
                   const float* __restrict__ Wl, const float* __restrict__ Wr,
                   const float* __restrict__ bias,
                   const float* __restrict__ lng, const float* __restrict__ lnb,
                   float* __restrict__ out, int n_nodes) {
    extern __shared__ float smem[];
    float* sW  = smem;               // [256][SROW]: rows 0..127 = Wl^T, 128..255 = Wr^T
    float* sIn = smem + 256 * SROW;  // [128][SROW]

    int tid = threadIdx.x;
    int cg = tid & 15, ng = tid >> 4;
    int c0 = cg * 8, ng8 = ng * 8;

    for (int i = tid; i < CC; i += 256) {
        int c = i >> 7, k = i & 127;
        sW[k * SROW + c]         = Wl[i];
        sW[(128 + k) * SROW + c] = Wr[i];
    }
    float gv[8], bv[8];
    unsigned long long bias2[4];
#pragma unroll
    for (int j = 0; j < 8; ++j) {
        gv[j] = __ldg(lng + c0 + j);
        bv[j] = __ldg(lnb + c0 + j);
    }
#pragma unroll
    for (int p = 0; p < 4; ++p)
        bias2[p] = pack2(__ldg(bias + c0 + 2 * p), __ldg(bias + c0 + 2 * p + 1));
    __syncthreads();

    int ntiles = (n_nodes + 127) >> 7;
    for (int t = blockIdx.x; t < ntiles; t += gridDim.x) {
        int t0 = t << 7;
        int valid = min(128, n_nodes - t0);

        unsigned long long acc[8][4];
#pragma unroll
        for (int r = 0; r < 8; ++r)
#pragma unroll
            for (int p = 0; p < 4; ++p) acc[r][p] = bias2[p];

        // phase 0: A = msg * inv_count
        for (int i = tid; i < 128 * 32; i += 256) {
            int n = i >> 5, c4 = (i & 31) << 2;
            float4 v = make_float4(0.f, 0.f, 0.f, 0.f);
            if (n < valid) {
                v = __ldg((const float4*)(msg + (size_t)(t0 + n) * C + c4));
                float s = __ldg(inv + t0 + n);
                v.x *= s; v.y *= s; v.z *= s; v.w *= s;
            }
            *(float4*)(sIn + n * SROW + c4) = v;
        }
        __syncthreads();
        mac_phase(sW, sIn, ng8, c0, acc);
        __syncthreads();

        // phase 1: B = x
        for (int i = tid; i < 128 * 32; i += 256) {
            int n = i >> 5, c4 = (i & 31) << 2;
            float4 v = make_float4(0.f, 0.f, 0.f, 0.f);
            if (n < valid)
                v = __ldg((const float4*)(xin + (size_t)(t0 + n) * C + c4));
            *(float4*)(sIn + n * SROW + c4) = v;
        }
        __syncthreads();
        mac_phase(sW + 128 * SROW, sIn, ng8, c0, acc);
        __syncthreads();

        // epilogue: LayerNorm (reduce across the 16 channel-group lanes) + ReLU
#pragma unroll
        for (int r = 0; r < 8; ++r) {
            float v[8];
#pragma unroll
            for (int p = 0; p < 4; ++p) unpack2(acc[r][p], v[2 * p], v[2 * p + 1]);
            float s = 0.f, q = 0.f;
#pragma unroll
            for (int j = 0; j < 8; ++j) { s += v[j]; q += v[j] * v[j]; }
#pragma unroll
            for (int m = 1; m < 16; m <<= 1) {
                s += __shfl_xor_sync(0xffffffffu, s, m);
                q += __shfl_xor_sync(0xffffffffu, q, m);
            }
            float mu = s * (1.f / 128.f);
            float var = q * (1.f / 128.f) - mu * mu;
            float rstd = rsqrtf(var + 1e-5f);
            int n = ng8 + r;
            if (n < valid) {
                float o[8];
#pragma unroll
                for (int j = 0; j < 8; ++j) {
                    float y = (v[j] - mu) * rstd * gv[j] + bv[j];
                    o[j] = fmaxf(y, 0.f);
                }
                float* po = out + (size_t)(t0 + n) * C + c0;
                *(float4*)po       = make_float4(o[0], o[1], o[2], o[3]);
                *(float4*)(po + 4) = make_float4(o[4], o[5], o[6], o[7]);
            }
        }
    }
}

// ---------------------------------------------------------------------------
// Host launcher
// ---------------------------------------------------------------------------
extern "C" void kernel_launch(void* const* d_in, const int* in_sizes, int n_in,
                              void* d_out, int out_size) {
    const float* x_user     = (const float*)d_in[0];
    const float* x_item     = (const float*)d_in[1];
    const int*   seed_time  = (const int*)d_in[2];
    const int*   time_user  = (const int*)d_in[3];
    const int*   time_item  = (const int*)d_in[4];
    const int*   batch_user = (const int*)d_in[5];
    const int*   batch_item = (const int*)d_in[6];
    const int*   src_ui     = (const int*)d_in[7];
    const int*   dst_ui     = (const int*)d_in[8];
    const int*   src_iu     = (const int*)d_in[9];
    const int*   dst_iu     = (const int*)d_in[10];
    const float* te_W_user  = (const float*)d_in[11];
    const float* te_b_user  = (const float*)d_in[12];
    const float* te_W_item  = (const float*)d_in[13];
    const float* te_b_item  = (const float*)d_in[14];
    const float* Wl_ui      = (const float*)d_in[15];
    const float* bl_ui      = (const float*)d_in[16];
    const float* Wr_ui      = (const float*)d_in[17];
    const float* Wl_iu      = (const float*)d_in[18];
    const float* bl_iu      = (const float*)d_in[19];
    const float* Wr_iu      = (const float*)d_in[20];
    const float* ln_g_user  = (const float*)d_in[21];
    const float* ln_b_user  = (const float*)d_in[22];
    const float* ln_g_item  = (const float*)d_in[23];
    const float* ln_b_item  = (const float*)d_in[24];
    float* outp = (float*)d_out;

    const int E = in_sizes[7];

    float *xu, *xi, *msgu, *msgi, *invu, *invi;
    int *cntu, *cnti;
    cudaGetSymbolAddress((void**)&xu,   g_xu);
    cudaGetSymbolAddress((void**)&xi,   g_xi);
    cudaGetSymbolAddress((void**)&msgu, g_msg_u);
    cudaGetSymbolAddress((void**)&msgi, g_msg_i);
    cudaGetSymbolAddress((void**)&cntu, g_cnt_u);
    cudaGetSymbolAddress((void**)&cnti, g_cnt_i);
    cudaGetSymbolAddress((void**)&invu, g_inv_u);
    cudaGetSymbolAddress((void**)&invi, g_inv_i);
    float* xu0 = xu;
    float* xu1 = xu + (size_t)NU * C;
    float* xi0 = xi;
    float* xi1 = xi + (size_t)NI * C;

    const int UPD_SMEM = UPD_SMEM_FLOATS * 4;
    const int TE_SMEM  = TE_SMEM_FLOATS * 4;
    cudaFuncSetAttribute(update_kernel,   cudaFuncAttributeMaxDynamicSharedMemorySize, UPD_SMEM);
    cudaFuncSetAttribute(temporal_kernel, cudaFuncAttributeMaxDynamicSharedMemorySize, TE_SMEM);

    const int NSM = 148;

    // --- degree counts (dst arrays are layer-invariant) ---
    zero_kernel<<<512, 256>>>((float4*)cntu, NU / 4);
    zero_kernel<<<512, 256>>>((float4*)cnti, NI / 4);
    count_kernel<<<2048, 256>>>(dst_ui, cnti, E);
    count_kernel<<<2048, 256>>>(dst_iu, cntu, E);
    inv_kernel<<<(NU + 255) / 256, 256>>>(cntu, invu, NU);
    inv_kernel<<<(NI + 255) / 256, 256>>>(cnti, invi, NI);

    // --- temporal encoder ---
    temporal_kernel<<<NSM, 256, TE_SMEM>>>(x_user, seed_time, time_user, batch_user,
                                           te_W_user, te_b_user, xu0, NU);
    temporal_kernel<<<NSM, 256, TE_SMEM>>>(x_item, seed_time, time_item, batch_item,
                                           te_W_item, te_b_item, xi0, NI);

    const float* cu = xu0;
    const float* ci = xi0;
    for (int l = 0; l < 2; ++l) {
        zero_kernel<<<4096, 256>>>((float4*)msgu, NU * C / 4);
        zero_kernel<<<4096, 256>>>((float4*)msgi, NI * C / 4);
        scatter_kernel<<<1184, 256>>>(cu, src_ui, dst_ui, msgi, E);
        scatter_kernel<<<1184, 256>>>(ci, src_iu, dst_iu, msgu, E);

        float* oi = (l == 1) ? (outp + (size_t)NU * C) : xi1;
        float* ou = (l == 1) ? outp : xu1;
        update_kernel<<<NSM, 256, UPD_SMEM>>>(msgi, invi, ci,
                                              Wl_ui + (size_t)l * CC, Wr_ui + (size_t)l * CC,
                                              bl_ui + (size_t)l * C,
                                              ln_g_item + (size_t)l * C, ln_b_item + (size_t)l * C,
                                              oi, NI);
        update_kernel<<<NSM, 256, UPD_SMEM>>>(msgu, invu, cu,
                                              Wl_iu + (size_t)l * CC, Wr_iu + (size_t)l * CC,
                                              bl_iu + (size_t)l * C,
                                              ln_g_user + (size_t)l * C, ln_b_user + (size_t)l * C,
                                              ou, NU);
        cu = xu1;
        ci = xi1;
    }
}